// round 8
// baseline (speedup 1.0000x reference)
#include <cuda_runtime.h>
#include <cstdint>
#include <math.h>

// ---------------------------------------------------------------------------
// Qwen3 attention block. Round 8 = Round 7 resubmitted (infra failure, never
// ran). Round-5 GEMM (scalar-LDS fragments, best) resized for 2 CTAs/SM:
// BM=128 BN=128, warp tile 32x64, launch_bounds(256,2) -> 16 warps/SM to hide
// LDS latency + barrier bubbles (R6 proved the kernel is latency-bound, not
// issue-bound). Flash/norm/prepass unchanged.
// ---------------------------------------------------------------------------

#define T_SEQ 2048
#define HID   4096
#define NQH   32
#define NKV   8
#define HD    128
#define QKV_N 6144
#define O_N   4096

__device__ float g_qkv[(size_t)T_SEQ * QKV_N];
__device__ float g_attn[(size_t)T_SEQ * O_N];
__device__ float g_hidr[(size_t)T_SEQ * HID];
__device__ float g_wqkvr[(size_t)HID * QKV_N];
__device__ float g_wor[(size_t)HID * O_N];

__device__ __forceinline__ float f2tf32(float x) {
    uint32_t u;
    asm("cvt.rna.tf32.f32 %0, %1;" : "=r"(u) : "f"(x));
    return __uint_as_float(u);
}

__device__ __forceinline__ void mma8(float& c0, float& c1, float& c2, float& c3,
                                     float a0, float a1, float a2, float a3,
                                     float b0, float b1) {
    asm volatile(
        "mma.sync.aligned.m16n8k8.row.col.f32.tf32.tf32.f32 "
        "{%0,%1,%2,%3}, {%4,%5,%6,%7}, {%8,%9}, {%0,%1,%2,%3};\n"
        : "+f"(c0), "+f"(c1), "+f"(c2), "+f"(c3)
        : "r"(__float_as_uint(a0)), "r"(__float_as_uint(a1)),
          "r"(__float_as_uint(a2)), "r"(__float_as_uint(a3)),
          "r"(__float_as_uint(b0)), "r"(__float_as_uint(b1)));
}

__device__ __forceinline__ uint32_t s2u(const void* p) {
    return (uint32_t)__cvta_generic_to_shared(p);
}
#define CPASYNC16(dst_u32, src_ptr) \
    asm volatile("cp.async.cg.shared.global [%0], [%1], 16;\n" \
                 :: "r"(dst_u32), "l"(src_ptr))

// ---------------------------------------------------------------------------
// Pipelined GEMM: C[M,N] = A[M,K] @ B[K,N], pre-rounded tf32 operands.
// Block 128x128, BK=32, 256 threads (8 warps, 4M x 2N, warp tile 32x64).
// 3-stage cp.async; 2 CTAs/SM via launch_bounds(256,2).
//   As[m][k] stride 36  -> word%32 = 4m+k (conflict-free for (tq,tr) lanes)
//   Bs[k][n] stride 136 -> word%32 = 8k+n (conflict-free for (tr,tq) lanes)
// ---------------------------------------------------------------------------
#define BM 128
#define BN 128
#define BK 32
#define ASTRD 36
#define BSTRD 136
#define STG_FLOATS (BM * ASTRD + BK * BSTRD)            // 8960
#define GEMM_SMEM (3 * STG_FLOATS * 4)                  // 107520 B

__global__ __launch_bounds__(256, 2)
void gemm_tf32_pipe(const float* __restrict__ A, const float* __restrict__ B,
                    float* __restrict__ C, int M, int N, int K) {
    extern __shared__ float sm[];

    const int tid  = threadIdx.x;
    const int warp = tid >> 5, lane = tid & 31;
    const int tq = lane >> 2, tr = lane & 3;
    const int wm = (warp & 3) * 32;
    const int wn = (warp >> 2) * 64;
    const size_t bm = (size_t)blockIdx.x * BM;
    const size_t bn = (size_t)blockIdx.y * BN;

    float c[2][8][4];
    #pragma unroll
    for (int mi = 0; mi < 2; mi++)
        #pragma unroll
        for (int ni = 0; ni < 8; ni++)
            #pragma unroll
            for (int e = 0; e < 4; e++) c[mi][ni][e] = 0.f;

    // staging coords: A 128x32 = 1024 float4 (4/thr), B 32x128 = 1024 float4
    const int arow = tid >> 3, acol = (tid & 7) * 4;
    const int brow = tid >> 5, bcol = (tid & 31) * 4;
    const int NT = K / BK;

    auto stage = [&](int kt, int s) {
        float* sa = sm + s * STG_FLOATS;
        float* sb = sa + BM * ASTRD;
        #pragma unroll
        for (int i = 0; i < 4; i++)
            CPASYNC16(s2u(sa + (arow + 32 * i) * ASTRD + acol),
                      A + (bm + arow + 32 * i) * (size_t)K + kt + acol);
        #pragma unroll
        for (int i = 0; i < 4; i++)
            CPASYNC16(s2u(sb + (brow + 8 * i) * BSTRD + bcol),
                      B + (size_t)(kt + brow + 8 * i) * N + bn + bcol);
        asm volatile("cp.async.commit_group;\n");
    };

    stage(0, 0);
    stage(BK, 1);

    for (int t = 0; t < NT; t++) {
        __syncthreads();                       // all warps done with stage (t-1)%3
        if (t + 2 < NT) {
            stage((t + 2) * BK, (t + 2) % 3);
            asm volatile("cp.async.wait_group 2;\n");
        } else if (t + 1 < NT) {
            asm volatile("cp.async.wait_group 1;\n");
        } else {
            asm volatile("cp.async.wait_group 0;\n");
        }
        __syncthreads();                       // stage t%3 visible

        const float* sa = sm + (t % 3) * STG_FLOATS;
        const float* sb = sa + BM * ASTRD;

        #pragma unroll
        for (int kk = 0; kk < 4; kk++) {
            const int k0 = 8 * kk + tr;
            float a[2][4];
            #pragma unroll
            for (int mi = 0; mi < 2; mi++) {
                const int r0 = wm + 16 * mi + tq;
                a[mi][0] = sa[r0 * ASTRD + k0];
                a[mi][1] = sa[(r0 + 8) * ASTRD + k0];
                a[mi][2] = sa[r0 * ASTRD + k0 + 4];
                a[mi][3] = sa[(r0 + 8) * ASTRD + k0 + 4];
            }
            float b[8][2];
            #pragma unroll
            for (int ni = 0; ni < 8; ni++) {
                const int col = wn + 8 * ni + tq;
                b[ni][0] = sb[k0 * BSTRD + col];
                b[ni][1] = sb[(k0 + 4) * BSTRD + col];
            }
            #pragma unroll
            for (int mi = 0; mi < 2; mi++)
                #pragma unroll
                for (int ni = 0; ni < 8; ni++)
                    mma8(c[mi][ni][0], c[mi][ni][1], c[mi][ni][2], c[mi][ni][3],
                         a[mi][0], a[mi][1], a[mi][2], a[mi][3],
                         b[ni][0], b[ni][1]);
        }
    }

    #pragma unroll
    for (int mi = 0; mi < 2; mi++) {
        #pragma unroll
        for (int ni = 0; ni < 8; ni++) {
            size_t r  = bm + wm + 16 * mi + tq;
            size_t cc = bn + wn + 8 * ni + 2 * tr;
            *(float2*)(C + r * N + cc)       = make_float2(c[mi][ni][0], c[mi][ni][1]);
            *(float2*)(C + (r + 8) * N + cc) = make_float2(c[mi][ni][2], c[mi][ni][3]);
        }
    }
}

// ---------------------------------------------------------------------------
// prepass: elementwise tf32 rounding
// ---------------------------------------------------------------------------
__global__ void round_copy(const float* __restrict__ src, float* __restrict__ dst,
                           int n4) {
    int i = blockIdx.x * blockDim.x + threadIdx.x;
    if (i < n4) {
        float4 v = ((const float4*)src)[i];
        v.x = f2tf32(v.x); v.y = f2tf32(v.y); v.z = f2tf32(v.z); v.w = f2tf32(v.w);
        ((float4*)dst)[i] = v;
    }
}

// ---------------------------------------------------------------------------
// Per-(token, head) RMSNorm + RoPE (unchanged).
// ---------------------------------------------------------------------------
__global__ void norm_rope(const float* __restrict__ qw, const float* __restrict__ kw) {
    const int t = blockIdx.x;
    const int h = blockIdx.y;
    float* base = g_qkv + (size_t)t * QKV_N + h * HD;

    __shared__ float xs[HD];
    __shared__ float red[4];
    const int j = threadIdx.x;

    float x = base[j];
    xs[j] = x;
    float ss = x * x;
    #pragma unroll
    for (int o = 16; o > 0; o >>= 1) ss += __shfl_xor_sync(0xffffffffu, ss, o);
    if ((j & 31) == 0) red[j >> 5] = ss;
    __syncthreads();

    float scale = rsqrtf((red[0] + red[1] + red[2] + red[3]) * (1.0f / HD) + 1e-6f);
    const float* w = (h < NQH) ? qw : kw;

    if (j < 64) {
        float x1 = xs[j]      * scale * w[j];
        float x2 = xs[j + 64] * scale * w[j + 64];
        float invf = exp2f(-(float)j * (19.931568569324174f / 64.0f));
        float ang = (float)t * invf;
        float s, cth;
        sincosf(ang, &s, &cth);
        base[j]      = x1 * cth - x2 * s;
        base[j + 64] = x2 * cth + x1 * s;
    }
}

// ---------------------------------------------------------------------------
// Flash attention (unchanged; epilogue stores tf32-rounded output).
// ---------------------------------------------------------------------------
#define KSTR 132
#define VSTR 136
#define PSTR 68

__global__ __launch_bounds__(128)
void flash_attn() {
    extern __shared__ float sm[];
    float (*Ks)[KSTR] = (float(*)[KSTR])sm;
    float (*Vs)[VSTR] = (float(*)[VSTR])(sm + 64 * KSTR);
    float (*Ps)[PSTR] = (float(*)[PSTR])(sm + 64 * KSTR + 64 * VSTR);

    const int h  = blockIdx.x;
    const int qb = blockIdx.y;
    const int kh = h >> 2;
    const int tid = threadIdx.x;
    const int warp = tid >> 5, lane = tid & 31;
    const int tq = lane >> 2, tr = lane & 3;
    const float scaling = 0.08838834764831845f;

    #pragma unroll
    for (int i = 0; i < 16; i++) {
        int f = tid + 128 * i;
        int row = f >> 5, c4 = (f & 31) * 4;
        float4 v = *(const float4*)(g_qkv + (size_t)(64 * qb + row) * QKV_N + h * HD + c4);
        v.x = f2tf32(v.x * scaling); v.y = f2tf32(v.y * scaling);
        v.z = f2tf32(v.z * scaling); v.w = f2tf32(v.w * scaling);
        *(float4*)&Ks[row][c4] = v;
    }
    __syncthreads();
    float qf[16][4];
    #pragma unroll
    for (int kk = 0; kk < 16; kk++) {
        int r0 = 16 * warp + tq, k0 = 8 * kk + tr;
        qf[kk][0] = Ks[r0][k0];
        qf[kk][1] = Ks[r0 + 8][k0];
        qf[kk][2] = Ks[r0][k0 + 4];
        qf[kk][3] = Ks[r0 + 8][k0 + 4];
    }
    __syncthreads();

    float o[16][4];
    #pragma unroll
    for (int ni = 0; ni < 16; ni++)
        #pragma unroll
        for (int e = 0; e < 4; e++) o[ni][e] = 0.f;
    float m1 = -1e30f, m2 = -1e30f, l1 = 0.f, l2 = 0.f;

    const int r1 = 16 * warp + tq, r2 = r1 + 8;

    for (int kb = 0; kb <= qb; kb++) {
        #pragma unroll
        for (int i = 0; i < 16; i++) {
            int f = tid + 128 * i;
            int row = f >> 5, c4 = (f & 31) * 4;
            const float* rp = g_qkv + (size_t)(64 * kb + row) * QKV_N;
            float4 kv = *(const float4*)(rp + 4096 + kh * HD + c4);
            kv.x = f2tf32(kv.x); kv.y = f2tf32(kv.y); kv.z = f2tf32(kv.z); kv.w = f2tf32(kv.w);
            *(float4*)&Ks[row][c4] = kv;
            float4 vv = *(const float4*)(rp + 5120 + kh * HD + c4);
            vv.x = f2tf32(vv.x); vv.y = f2tf32(vv.y); vv.z = f2tf32(vv.z); vv.w = f2tf32(vv.w);
            *(float4*)&Vs[row][c4] = vv;
        }
        __syncthreads();

        float s[8][4];
        #pragma unroll
        for (int ni = 0; ni < 8; ni++)
            #pragma unroll
            for (int e = 0; e < 4; e++) s[ni][e] = 0.f;

        #pragma unroll
        for (int kk = 0; kk < 16; kk++) {
            const int d0 = 8 * kk + tr;
            #pragma unroll
            for (int ni = 0; ni < 8; ni++) {
                float b0 = Ks[8 * ni + tq][d0];
                float b1 = Ks[8 * ni + tq][d0 + 4];
                mma8(s[ni][0], s[ni][1], s[ni][2], s[ni][3],
                     qf[kk][0], qf[kk][1], qf[kk][2], qf[kk][3], b0, b1);
            }
        }

        if (kb == qb) {
            #pragma unroll
            for (int ni = 0; ni < 8; ni++) {
                int c0 = 8 * ni + 2 * tr;
                if (c0     > r1) s[ni][0] = -1e30f;
                if (c0 + 1 > r1) s[ni][1] = -1e30f;
                if (c0     > r2) s[ni][2] = -1e30f;
                if (c0 + 1 > r2) s[ni][3] = -1e30f;
            }
        }

        float tm1 = -1e30f, tm2 = -1e30f;
        #pragma unroll
        for (int ni = 0; ni < 8; ni++) {
            tm1 = fmaxf(tm1, fmaxf(s[ni][0], s[ni][1]));
            tm2 = fmaxf(tm2, fmaxf(s[ni][2], s[ni][3]));
        }
        tm1 = fmaxf(tm1, __shfl_xor_sync(0xffffffffu, tm1, 1));
        tm1 = fmaxf(tm1, __shfl_xor_sync(0xffffffffu, tm1, 2));
        tm2 = fmaxf(tm2, __shfl_xor_sync(0xffffffffu, tm2, 1));
        tm2 = fmaxf(tm2, __shfl_xor_sync(0xffffffffu, tm2, 2));

        float nm1 = fmaxf(m1, tm1), nm2 = fmaxf(m2, tm2);
        float a1 = __expf(m1 - nm1), a2 = __expf(m2 - nm2);

        float rs1 = 0.f, rs2 = 0.f;
        #pragma unroll
        for (int ni = 0; ni < 8; ni++) {
            int c0 = 8 * ni + 2 * tr;
            float p0 = __expf(s[ni][0] - nm1);
            float p1 = __expf(s[ni][1] - nm1);
            float p2 = __expf(s[ni][2] - nm2);
            float p3 = __expf(s[ni][3] - nm2);
            rs1 += p0 + p1; rs2 += p2 + p3;
            Ps[r1][c0]     = f2tf32(p0);
            Ps[r1][c0 + 1] = f2tf32(p1);
            Ps[r2][c0]     = f2tf32(p2);
            Ps[r2][c0 + 1] = f2tf32(p3);
        }
        rs1 += __shfl_xor_sync(0xffffffffu, rs1, 1);
        rs1 += __shfl_xor_sync(0xffffffffu, rs1, 2);
        rs2 += __shfl_xor_sync(0xffffffffu, rs2, 1);
        rs2 += __shfl_xor_sync(0xffffffffu, rs2, 2);

        l1 = l1 * a1 + rs1; l2 = l2 * a2 + rs2;
        m1 = nm1; m2 = nm2;

        #pragma unroll
        for (int ni = 0; ni < 16; ni++) {
            o[ni][0] *= a1; o[ni][1] *= a1;
            o[ni][2] *= a2; o[ni][3] *= a2;
        }

        __syncwarp();

        #pragma unroll
        for (int kp = 0; kp < 8; kp++) {
            float a0  = Ps[r1][8 * kp + tr];
            float a1f = Ps[r2][8 * kp + tr];
            float a2f = Ps[r1][8 * kp + tr + 4];
            float a3f = Ps[r2][8 * kp + tr + 4];
            #pragma unroll
            for (int ni = 0; ni < 16; ni++) {
                float b0 = Vs[8 * kp + tr][8 * ni + tq];
                float b1 = Vs[8 * kp + tr + 4][8 * ni + tq];
                mma8(o[ni][0], o[ni][1], o[ni][2], o[ni][3], a0, a1f, a2f, a3f, b0, b1);
            }
        }
        __syncthreads();
    }

    const float inv1 = 1.0f / l1, inv2 = 1.0f / l2;
    const size_t gr1 = (size_t)(64 * qb) + r1;
    #pragma unroll
    for (int ni = 0; ni < 16; ni++) {
        int d = 8 * ni + 2 * tr;
        *(float2*)(g_attn + gr1 * O_N + h * HD + d) =
            make_float2(f2tf32(o[ni][0] * inv1), f2tf32(o[ni][1] * inv1));
        *(float2*)(g_attn + (gr1 + 8) * O_N + h * HD + d) =
            make_float2(f2tf32(o[ni][2] * inv2), f2tf32(o[ni][3] * inv2));
    }
}

// ---------------------------------------------------------------------------
extern "C" void kernel_launch(void* const* d_in, const int* in_sizes, int n_in,
                              void* d_out, int out_size) {
    const float* hidden = (const float*)d_in[1];
    const float* w_qkv  = (const float*)d_in[2];
    const float* qw     = (const float*)d_in[3];
    const float* kw     = (const float*)d_in[4];
    const float* w_o    = (const float*)d_in[5];
    float* out = (float*)d_out;

    void *qkv_p = nullptr, *attn_p = nullptr, *hidr_p = nullptr;
    void *wqkvr_p = nullptr, *wor_p = nullptr;
    cudaGetSymbolAddress(&qkv_p, g_qkv);
    cudaGetSymbolAddress(&attn_p, g_attn);
    cudaGetSymbolAddress(&hidr_p, g_hidr);
    cudaGetSymbolAddress(&wqkvr_p, g_wqkvr);
    cudaGetSymbolAddress(&wor_p, g_wor);

    static bool attr_set = false;
    if (!attr_set) {
        cudaFuncSetAttribute(gemm_tf32_pipe,
                             cudaFuncAttributeMaxDynamicSharedMemorySize, GEMM_SMEM);
        const int SMEM_ATTN = (64 * KSTR + 64 * VSTR + 64 * PSTR) * 4;
        cudaFuncSetAttribute(flash_attn,
                             cudaFuncAttributeMaxDynamicSharedMemorySize, SMEM_ATTN);
        attr_set = true;
    }
    const int SMEM_ATTN = (64 * KSTR + 64 * VSTR + 64 * PSTR) * 4;  // 86016 B

    round_copy<<<(T_SEQ * HID / 4 + 255) / 256, 256>>>(
        hidden, (float*)hidr_p, T_SEQ * HID / 4);
    round_copy<<<(HID * QKV_N / 4 + 255) / 256, 256>>>(
        w_qkv, (float*)wqkvr_p, HID * QKV_N / 4);
    round_copy<<<(HID * O_N / 4 + 255) / 256, 256>>>(
        w_o, (float*)wor_p, HID * O_N / 4);

    gemm_tf32_pipe<<<dim3(T_SEQ / BM, QKV_N / BN), 256, GEMM_SMEM>>>(
        (const float*)hidr_p, (const float*)wqkvr_p, (float*)qkv_p,
        T_SEQ, QKV_N, HID);

    norm_rope<<<dim3(T_SEQ, NQH + NKV), HD>>>(qw, kw);

    flash_attn<<<dim3(NQH, T_SEQ / 64), 128, SMEM_ATTN>>>();

    gemm_tf32_pipe<<<dim3(T_SEQ / BM, O_N / BN), 256, GEMM_SMEM>>>(
        (const float*)attn_p, (const float*)wor_p, out,
        T_SEQ, O_N, HID);
}

// round 10
// speedup vs baseline: 1.1151x; 1.1151x over previous
#include <cuda_runtime.h>
#include <cstdint>
#include <math.h>

// ---------------------------------------------------------------------------
// Qwen3 attention block. Round 10 = Round 9 resubmitted (infra failure, never
// ran). R5 config (best, 1479us) with the GEMM restructured to a 4-stage
// cp.async ring + ONE __syncthreads per k-iter (was 2). Discriminates
// barrier-bubble vs HMMA-ceiling hypotheses. Flash/norm/prepass identical
// to R5.
// ---------------------------------------------------------------------------

#define T_SEQ 2048
#define HID   4096
#define NQH   32
#define NKV   8
#define HD    128
#define QKV_N 6144
#define O_N   4096

__device__ float g_qkv[(size_t)T_SEQ * QKV_N];
__device__ float g_attn[(size_t)T_SEQ * O_N];
__device__ float g_hidr[(size_t)T_SEQ * HID];
__device__ float g_wqkvr[(size_t)HID * QKV_N];
__device__ float g_wor[(size_t)HID * O_N];

__device__ __forceinline__ float f2tf32(float x) {
    uint32_t u;
    asm("cvt.rna.tf32.f32 %0, %1;" : "=r"(u) : "f"(x));
    return __uint_as_float(u);
}

__device__ __forceinline__ void mma8(float& c0, float& c1, float& c2, float& c3,
                                     float a0, float a1, float a2, float a3,
                                     float b0, float b1) {
    asm volatile(
        "mma.sync.aligned.m16n8k8.row.col.f32.tf32.tf32.f32 "
        "{%0,%1,%2,%3}, {%4,%5,%6,%7}, {%8,%9}, {%0,%1,%2,%3};\n"
        : "+f"(c0), "+f"(c1), "+f"(c2), "+f"(c3)
        : "r"(__float_as_uint(a0)), "r"(__float_as_uint(a1)),
          "r"(__float_as_uint(a2)), "r"(__float_as_uint(a3)),
          "r"(__float_as_uint(b0)), "r"(__float_as_uint(b1)));
}

__device__ __forceinline__ uint32_t s2u(const void* p) {
    return (uint32_t)__cvta_generic_to_shared(p);
}
#define CPASYNC16(dst_u32, src_ptr) \
    asm volatile("cp.async.cg.shared.global [%0], [%1], 16;\n" \
                 :: "r"(dst_u32), "l"(src_ptr))

// ---------------------------------------------------------------------------
// Pipelined GEMM: C[M,N] = A[M,K] @ B[K,N], pre-rounded tf32 operands.
// Block 128x256, BK=32, 256 threads (8 warps, 2M x 4N, warp tile 64x64).
// 4-stage cp.async ring, prefetch distance 2, ONE __syncthreads per k-iter.
// Hazard proof: prefetch at iter t writes buf (t+2)%4, last read at compute
// t-2; the barrier inside iter t-1 (which every warp passed before issuing
// iter-t prefetch) ordered compute t-2 completion. cp.async visibility:
// every thread waits its own groups (wait_group 2) then the barrier
// publishes stage t to all warps.
//   As[m][k] stride 36  -> word%32 = 4m+k (conflict-free fragment reads)
//   Bs[k][n] stride 264 -> word%32 = 8k+n
// ---------------------------------------------------------------------------
#define BM 128
#define BN 256
#define BK 32
#define ASTRD 36
#define BSTRD 264
#define STG_FLOATS (BM * ASTRD + BK * BSTRD)            // 13056
#define GEMM_SMEM (4 * STG_FLOATS * 4)                  // 208896 B

__global__ __launch_bounds__(256, 1)
void gemm_tf32_pipe(const float* __restrict__ A, const float* __restrict__ B,
                    float* __restrict__ C, int M, int N, int K) {
    extern __shared__ float sm[];

    const int tid  = threadIdx.x;
    const int warp = tid >> 5, lane = tid & 31;
    const int tq = lane >> 2, tr = lane & 3;
    const int wm = (warp & 1) * 64;
    const int wn = (warp >> 1) * 64;
    const size_t bm = (size_t)blockIdx.x * BM;
    const size_t bn = (size_t)blockIdx.y * BN;

    float c[4][8][4];
    #pragma unroll
    for (int mi = 0; mi < 4; mi++)
        #pragma unroll
        for (int ni = 0; ni < 8; ni++)
            #pragma unroll
            for (int e = 0; e < 4; e++) c[mi][ni][e] = 0.f;

    const int arow = tid >> 3, acol = (tid & 7) * 4;
    const int brow = tid >> 6, bcol = (tid & 63) * 4;
    const int NT = K / BK;

    auto stage = [&](int kt, int s) {
        float* sa = sm + s * STG_FLOATS;
        float* sb = sa + BM * ASTRD;
        #pragma unroll
        for (int i = 0; i < 4; i++)
            CPASYNC16(s2u(sa + (arow + 32 * i) * ASTRD + acol),
                      A + (bm + arow + 32 * i) * (size_t)K + kt + acol);
        #pragma unroll
        for (int i = 0; i < 8; i++)
            CPASYNC16(s2u(sb + (brow + 4 * i) * BSTRD + bcol),
                      B + (size_t)(kt + brow + 4 * i) * N + bn + bcol);
        asm volatile("cp.async.commit_group;\n");
    };

    stage(0, 0);
    stage(BK, 1);

    for (int t = 0; t < NT; t++) {
        if (t + 2 < NT) {
            stage((t + 2) * BK, (t + 2) & 3);
            asm volatile("cp.async.wait_group 2;\n");
        } else if (t + 1 < NT) {
            asm volatile("cp.async.wait_group 1;\n");
        } else {
            asm volatile("cp.async.wait_group 0;\n");
        }
        __syncthreads();   // single barrier: publishes stage t, orders reuse

        const float* sa = sm + (t & 3) * STG_FLOATS;
        const float* sb = sa + BM * ASTRD;

        #pragma unroll
        for (int kk = 0; kk < 4; kk++) {
            const int k0 = 8 * kk + tr;
            float a[4][4];
            #pragma unroll
            for (int mi = 0; mi < 4; mi++) {
                const int r0 = wm + 16 * mi + tq;
                a[mi][0] = sa[r0 * ASTRD + k0];
                a[mi][1] = sa[(r0 + 8) * ASTRD + k0];
                a[mi][2] = sa[r0 * ASTRD + k0 + 4];
                a[mi][3] = sa[(r0 + 8) * ASTRD + k0 + 4];
            }
            float b[8][2];
            #pragma unroll
            for (int ni = 0; ni < 8; ni++) {
                const int col = wn + 8 * ni + tq;
                b[ni][0] = sb[k0 * BSTRD + col];
                b[ni][1] = sb[(k0 + 4) * BSTRD + col];
            }
            #pragma unroll
            for (int mi = 0; mi < 4; mi++)
                #pragma unroll
                for (int ni = 0; ni < 8; ni++)
                    mma8(c[mi][ni][0], c[mi][ni][1], c[mi][ni][2], c[mi][ni][3],
                         a[mi][0], a[mi][1], a[mi][2], a[mi][3],
                         b[ni][0], b[ni][1]);
        }
    }

    #pragma unroll
    for (int mi = 0; mi < 4; mi++) {
        #pragma unroll
        for (int ni = 0; ni < 8; ni++) {
            size_t r  = bm + wm + 16 * mi + tq;
            size_t cc = bn + wn + 8 * ni + 2 * tr;
            *(float2*)(C + r * N + cc)       = make_float2(c[mi][ni][0], c[mi][ni][1]);
            *(float2*)(C + (r + 8) * N + cc) = make_float2(c[mi][ni][2], c[mi][ni][3]);
        }
    }
}

// ---------------------------------------------------------------------------
// prepass: elementwise tf32 rounding
// ---------------------------------------------------------------------------
__global__ void round_copy(const float* __restrict__ src, float* __restrict__ dst,
                           int n4) {
    int i = blockIdx.x * blockDim.x + threadIdx.x;
    if (i < n4) {
        float4 v = ((const float4*)src)[i];
        v.x = f2tf32(v.x); v.y = f2tf32(v.y); v.z = f2tf32(v.z); v.w = f2tf32(v.w);
        ((float4*)dst)[i] = v;
    }
}

// ---------------------------------------------------------------------------
// Per-(token, head) RMSNorm + RoPE (unchanged).
// ---------------------------------------------------------------------------
__global__ void norm_rope(const float* __restrict__ qw, const float* __restrict__ kw) {
    const int t = blockIdx.x;
    const int h = blockIdx.y;
    float* base = g_qkv + (size_t)t * QKV_N + h * HD;

    __shared__ float xs[HD];
    __shared__ float red[4];
    const int j = threadIdx.x;

    float x = base[j];
    xs[j] = x;
    float ss = x * x;
    #pragma unroll
    for (int o = 16; o > 0; o >>= 1) ss += __shfl_xor_sync(0xffffffffu, ss, o);
    if ((j & 31) == 0) red[j >> 5] = ss;
    __syncthreads();

    float scale = rsqrtf((red[0] + red[1] + red[2] + red[3]) * (1.0f / HD) + 1e-6f);
    const float* w = (h < NQH) ? qw : kw;

    if (j < 64) {
        float x1 = xs[j]      * scale * w[j];
        float x2 = xs[j + 64] * scale * w[j + 64];
        float invf = exp2f(-(float)j * (19.931568569324174f / 64.0f));
        float ang = (float)t * invf;
        float s, cth;
        sincosf(ang, &s, &cth);
        base[j]      = x1 * cth - x2 * s;
        base[j + 64] = x2 * cth + x1 * s;
    }
}

// ---------------------------------------------------------------------------
// Flash attention (unchanged; epilogue stores tf32-rounded output).
// ---------------------------------------------------------------------------
#define KSTR 132
#define VSTR 136
#define PSTR 68

__global__ __launch_bounds__(128)
void flash_attn() {
    extern __shared__ float sm[];
    float (*Ks)[KSTR] = (float(*)[KSTR])sm;
    float (*Vs)[VSTR] = (float(*)[VSTR])(sm + 64 * KSTR);
    float (*Ps)[PSTR] = (float(*)[PSTR])(sm + 64 * KSTR + 64 * VSTR);

    const int h  = blockIdx.x;
    const int qb = blockIdx.y;
    const int kh = h >> 2;
    const int tid = threadIdx.x;
    const int warp = tid >> 5, lane = tid & 31;
    const int tq = lane >> 2, tr = lane & 3;
    const float scaling = 0.08838834764831845f;

    #pragma unroll
    for (int i = 0; i < 16; i++) {
        int f = tid + 128 * i;
        int row = f >> 5, c4 = (f & 31) * 4;
        float4 v = *(const float4*)(g_qkv + (size_t)(64 * qb + row) * QKV_N + h * HD + c4);
        v.x = f2tf32(v.x * scaling); v.y = f2tf32(v.y * scaling);
        v.z = f2tf32(v.z * scaling); v.w = f2tf32(v.w * scaling);
        *(float4*)&Ks[row][c4] = v;
    }
    __syncthreads();
    float qf[16][4];
    #pragma unroll
    for (int kk = 0; kk < 16; kk++) {
        int r0 = 16 * warp + tq, k0 = 8 * kk + tr;
        qf[kk][0] = Ks[r0][k0];
        qf[kk][1] = Ks[r0 + 8][k0];
        qf[kk][2] = Ks[r0][k0 + 4];
        qf[kk][3] = Ks[r0 + 8][k0 + 4];
    }
    __syncthreads();

    float o[16][4];
    #pragma unroll
    for (int ni = 0; ni < 16; ni++)
        #pragma unroll
        for (int e = 0; e < 4; e++) o[ni][e] = 0.f;
    float m1 = -1e30f, m2 = -1e30f, l1 = 0.f, l2 = 0.f;

    const int r1 = 16 * warp + tq, r2 = r1 + 8;

    for (int kb = 0; kb <= qb; kb++) {
        #pragma unroll
        for (int i = 0; i < 16; i++) {
            int f = tid + 128 * i;
            int row = f >> 5, c4 = (f & 31) * 4;
            const float* rp = g_qkv + (size_t)(64 * kb + row) * QKV_N;
            float4 kv = *(const float4*)(rp + 4096 + kh * HD + c4);
            kv.x = f2tf32(kv.x); kv.y = f2tf32(kv.y); kv.z = f2tf32(kv.z); kv.w = f2tf32(kv.w);
            *(float4*)&Ks[row][c4] = kv;
            float4 vv = *(const float4*)(rp + 5120 + kh * HD + c4);
            vv.x = f2tf32(vv.x); vv.y = f2tf32(vv.y); vv.z = f2tf32(vv.z); vv.w = f2tf32(vv.w);
            *(float4*)&Vs[row][c4] = vv;
        }
        __syncthreads();

        float s[8][4];
        #pragma unroll
        for (int ni = 0; ni < 8; ni++)
            #pragma unroll
            for (int e = 0; e < 4; e++) s[ni][e] = 0.f;

        #pragma unroll
        for (int kk = 0; kk < 16; kk++) {
            const int d0 = 8 * kk + tr;
            #pragma unroll
            for (int ni = 0; ni < 8; ni++) {
                float b0 = Ks[8 * ni + tq][d0];
                float b1 = Ks[8 * ni + tq][d0 + 4];
                mma8(s[ni][0], s[ni][1], s[ni][2], s[ni][3],
                     qf[kk][0], qf[kk][1], qf[kk][2], qf[kk][3], b0, b1);
            }
        }

        if (kb == qb) {
            #pragma unroll
            for (int ni = 0; ni < 8; ni++) {
                int c0 = 8 * ni + 2 * tr;
                if (c0     > r1) s[ni][0] = -1e30f;
                if (c0 + 1 > r1) s[ni][1] = -1e30f;
                if (c0     > r2) s[ni][2] = -1e30f;
                if (c0 + 1 > r2) s[ni][3] = -1e30f;
            }
        }

        float tm1 = -1e30f, tm2 = -1e30f;
        #pragma unroll
        for (int ni = 0; ni < 8; ni++) {
            tm1 = fmaxf(tm1, fmaxf(s[ni][0], s[ni][1]));
            tm2 = fmaxf(tm2, fmaxf(s[ni][2], s[ni][3]));
        }
        tm1 = fmaxf(tm1, __shfl_xor_sync(0xffffffffu, tm1, 1));
        tm1 = fmaxf(tm1, __shfl_xor_sync(0xffffffffu, tm1, 2));
        tm2 = fmaxf(tm2, __shfl_xor_sync(0xffffffffu, tm2, 1));
        tm2 = fmaxf(tm2, __shfl_xor_sync(0xffffffffu, tm2, 2));

        float nm1 = fmaxf(m1, tm1), nm2 = fmaxf(m2, tm2);
        float a1 = __expf(m1 - nm1), a2 = __expf(m2 - nm2);

        float rs1 = 0.f, rs2 = 0.f;
        #pragma unroll
        for (int ni = 0; ni < 8; ni++) {
            int c0 = 8 * ni + 2 * tr;
            float p0 = __expf(s[ni][0] - nm1);
            float p1 = __expf(s[ni][1] - nm1);
            float p2 = __expf(s[ni][2] - nm2);
            float p3 = __expf(s[ni][3] - nm2);
            rs1 += p0 + p1; rs2 += p2 + p3;
            Ps[r1][c0]     = f2tf32(p0);
            Ps[r1][c0 + 1] = f2tf32(p1);
            Ps[r2][c0]     = f2tf32(p2);
            Ps[r2][c0 + 1] = f2tf32(p3);
        }
        rs1 += __shfl_xor_sync(0xffffffffu, rs1, 1);
        rs1 += __shfl_xor_sync(0xffffffffu, rs1, 2);
        rs2 += __shfl_xor_sync(0xffffffffu, rs2, 1);
        rs2 += __shfl_xor_sync(0xffffffffu, rs2, 2);

        l1 = l1 * a1 + rs1; l2 = l2 * a2 + rs2;
        m1 = nm1; m2 = nm2;

        #pragma unroll
        for (int ni = 0; ni < 16; ni++) {
            o[ni][0] *= a1; o[ni][1] *= a1;
            o[ni][2] *= a2; o[ni][3] *= a2;
        }

        __syncwarp();

        #pragma unroll
        for (int kp = 0; kp < 8; kp++) {
            float a0  = Ps[r1][8 * kp + tr];
            float a1f = Ps[r2][8 * kp + tr];
            float a2f = Ps[r1][8 * kp + tr + 4];
            float a3f = Ps[r2][8 * kp + tr + 4];
            #pragma unroll
            for (int ni = 0; ni < 16; ni++) {
                float b0 = Vs[8 * kp + tr][8 * ni + tq];
                float b1 = Vs[8 * kp + tr + 4][8 * ni + tq];
                mma8(o[ni][0], o[ni][1], o[ni][2], o[ni][3], a0, a1f, a2f, a3f, b0, b1);
            }
        }
        __syncthreads();
    }

    const float inv1 = 1.0f / l1, inv2 = 1.0f / l2;
    const size_t gr1 = (size_t)(64 * qb) + r1;
    #pragma unroll
    for (int ni = 0; ni < 16; ni++) {
        int d = 8 * ni + 2 * tr;
        *(float2*)(g_attn + gr1 * O_N + h * HD + d) =
            make_float2(f2tf32(o[ni][0] * inv1), f2tf32(o[ni][1] * inv1));
        *(float2*)(g_attn + (gr1 + 8) * O_N + h * HD + d) =
            make_float2(f2tf32(o[ni][2] * inv2), f2tf32(o[ni][3] * inv2));
    }
}

// ---------------------------------------------------------------------------
extern "C" void kernel_launch(void* const* d_in, const int* in_sizes, int n_in,
                              void* d_out, int out_size) {
    const float* hidden = (const float*)d_in[1];
    const float* w_qkv  = (const float*)d_in[2];
    const float* qw     = (const float*)d_in[3];
    const float* kw     = (const float*)d_in[4];
    const float* w_o    = (const float*)d_in[5];
    float* out = (float*)d_out;

    void *qkv_p = nullptr, *attn_p = nullptr, *hidr_p = nullptr;
    void *wqkvr_p = nullptr, *wor_p = nullptr;
    cudaGetSymbolAddress(&qkv_p, g_qkv);
    cudaGetSymbolAddress(&attn_p, g_attn);
    cudaGetSymbolAddress(&hidr_p, g_hidr);
    cudaGetSymbolAddress(&wqkvr_p, g_wqkvr);
    cudaGetSymbolAddress(&wor_p, g_wor);

    static bool attr_set = false;
    if (!attr_set) {
        cudaFuncSetAttribute(gemm_tf32_pipe,
                             cudaFuncAttributeMaxDynamicSharedMemorySize, GEMM_SMEM);
        const int SMEM_ATTN = (64 * KSTR + 64 * VSTR + 64 * PSTR) * 4;
        cudaFuncSetAttribute(flash_attn,
                             cudaFuncAttributeMaxDynamicSharedMemorySize, SMEM_ATTN);
        attr_set = true;
    }
    const int SMEM_ATTN = (64 * KSTR + 64 * VSTR + 64 * PSTR) * 4;  // 86016 B

    round_copy<<<(T_SEQ * HID / 4 + 255) / 256, 256>>>(
        hidden, (float*)hidr_p, T_SEQ * HID / 4);
    round_copy<<<(HID * QKV_N / 4 + 255) / 256, 256>>>(
        w_qkv, (float*)wqkvr_p, HID * QKV_N / 4);
    round_copy<<<(HID * O_N / 4 + 255) / 256, 256>>>(
        w_o, (float*)wor_p, HID * O_N / 4);

    gemm_tf32_pipe<<<dim3(T_SEQ / BM, QKV_N / BN), 256, GEMM_SMEM>>>(
        (const float*)hidr_p, (const float*)wqkvr_p, (float*)qkv_p,
        T_SEQ, QKV_N, HID);

    norm_rope<<<dim3(T_SEQ, NQH + NKV), HD>>>(qw, kw);

    flash_attn<<<dim3(NQH, T_SEQ / 64), 128, SMEM_ATTN>>>();

    gemm_tf32_pipe<<<dim3(T_SEQ / BM, O_N / BN), 256, GEMM_SMEM>>>(
        (const float*)attn_p, (const float*)wor_p, out,
        T_SEQ, O_N, HID);
}